// round 12
// baseline (speedup 1.0000x reference)
#include <cuda_runtime.h>
#include <cuda_fp16.h>
#include <cstdint>

// SimpleGNNBlock: out[b,k] = sum_p relu( relu(feats[b,p,:] @ W1 + b1) @ W2 + b2 )
// feats = [dx, dy, 1/sqrt(dx^2+dy^2+1e-6), m_p],  B=32768, P=128, H=64.
//
// R12: champion R5 structure (both layers on MMA, h fp16 via smem, bias
// folded into MMAs, 64x16 layer-2 warp tiles, 3 CTAs/SM) with fragment
// movement moved to matrix instructions: ldmatrix.x4 for layer-2 A reads
// (64 LDS.32 -> 16 LDSM) and stmatrix.x4 for layer-1 h stores
// (16 STS.32 -> 4 STSM). Same layout (HW=36, conflict-free), same math.

#define BATCHES 32768
#define PP 128
#define HH 64
#define GRID 4096
#define BPC (BATCHES / GRID)    // 8
#define HW 36                   // h row stride in words; 36%32==4 -> conflict-free

__device__ __forceinline__ uint32_t f2tf32(float x) {
    uint32_t u;
    asm("cvt.rna.tf32.f32 %0, %1;" : "=r"(u) : "f"(x));
    return u;
}
// pack two fp32 -> f16x2 {lo, hi}
__device__ __forceinline__ uint32_t pack_f16(float lo, float hi) {
    uint32_t u;
    asm("cvt.rn.f16x2.f32 %0, %1, %2;" : "=r"(u) : "f"(hi), "f"(lo));
    return u;
}

__global__ __launch_bounds__(256, 3)
void gnn_kernel(const float* __restrict__ planet_xy,   // (B,P,2)
                const float* __restrict__ planet_m,    // (P)
                const float* __restrict__ ast_xy,      // (B,2)
                const float* __restrict__ W1,          // (4,H)
                const float* __restrict__ b1,          // (H)
                const float* __restrict__ W2,          // (H,H) [j][k]
                const float* __restrict__ b2,          // (H)
                float* __restrict__ out)               // (B,H)
{
    __shared__ uint32_t h2[128 * HW];   // h as fp16x2 pairs, stride HW words
    __shared__ uint4    feats_s[PP];    // tf32 bits {dx,dy,inv,m}
    __shared__ float    sacc[HH];

    const int tid  = threadIdx.x;
    const int lane = tid & 31;
    const int w    = tid >> 5;     // warp 0..7
    const int g    = lane >> 2;    // group 0..7
    const int t    = lane & 3;     // thread-in-group 0..3
    const int mg   = w >> 2;       // m-group 0..1 (rows mg*64 .. +63)
    const int ng   = w & 3;        // n-group 0..3 (cols ng*16 .. +15)

    // shared-space byte address of h2 for ldmatrix/stmatrix
    const uint32_t h2base = (uint32_t)__cvta_generic_to_shared(h2);
    // lane-mapped row/chunk offsets (m8n8 tiles): row = (lane&15), 16B chunk
    // select = lane>>4.  Byte offset within h2:
    const uint32_t lmoff = (uint32_t)(((lane & 15) * HW + (lane >> 4) * 4) * 4);
    // stmatrix base: this warp's 16 rows start at w*16
    const uint32_t st_base = h2base + (uint32_t)(w * 16 * HW * 4) + lmoff;

    // ---- W2 fp16 B-fragments (m16n8k16 row.col): b0={B[2t][g],B[2t+1][g]},
    //      b1={B[2t+8][g],B[2t+9][g]}, B[k][n]=W2[k][col], col=(ng*2+n2)*8+g.
    uint32_t b2f0[2][4], b2f1[2][4], bbias[2];
    #pragma unroll
    for (int n2 = 0; n2 < 2; ++n2) {
        int col = (ng * 2 + n2) * 8 + g;
        #pragma unroll
        for (int kt = 0; kt < 4; ++kt) {
            b2f0[n2][kt] = pack_f16(W2[(kt * 16 + 2 * t)     * HH + col],
                                    W2[(kt * 16 + 2 * t + 1) * HH + col]);
            b2f1[n2][kt] = pack_f16(W2[(kt * 16 + 2 * t + 8) * HH + col],
                                    W2[(kt * 16 + 2 * t + 9) * HH + col]);
        }
        bbias[n2] = (t == 0) ? pack_f16(b2[col], 0.0f) : 0u;
    }
    const uint32_t abias = (t == 0) ? 0x00003C00u : 0u;   // {lo=1.0h, hi=0}

    // ---- W1 tf32 B-fragments (m16n8k8): b0=B[t][col]=W1[t][col],
    //      b1=B[t+4][col] = b1[col] if t==0 (bias row), else 0.
    uint32_t w1x[8], w1y[8];
    #pragma unroll
    for (int n = 0; n < 8; ++n) {
        int col = n * 8 + g;
        w1x[n] = f2tf32(W1[t * HH + col]);
        w1y[n] = (t == 0) ? f2tf32(b1[col]) : 0u;
    }
    const uint32_t a1pad = (t == 0) ? 0x3f800000u : 0u;   // 1.0f (exact tf32)

    uint32_t m32 = 0;
    if (tid < PP) m32 = f2tf32(planet_m[tid]);

    if (tid < HH) sacc[tid] = 0.0f;

    for (int it = 0; it < BPC; ++it) {
        const int b = blockIdx.x + it * GRID;

        // ---- feats (tf32 bits) ----
        if (tid < PP) {
            float2 pxy = reinterpret_cast<const float2*>(planet_xy)[b * PP + tid];
            float ax = ast_xy[2 * b], ay = ast_xy[2 * b + 1];
            float dx = pxy.x - ax;
            float dy = pxy.y - ay;
            float inv = rsqrtf(fmaf(dx, dx, fmaf(dy, dy, 1e-6f)));
            feats_s[tid] = make_uint4(f2tf32(dx), f2tf32(dy), f2tf32(inv), m32);
        }
        __syncthreads();

        // ---- layer 1: warp w owns m-tile w (16 rows), all 8 col-tiles.
        //      h fragments written with stmatrix.x4 per n-pair. ----
        {
            const uint32_t* fu = reinterpret_cast<const uint32_t*>(feats_s);
            uint32_t a0 = fu[(w * 16 + g)     * 4 + t];
            uint32_t a1 = fu[(w * 16 + g + 8) * 4 + t];
            #pragma unroll
            for (int np = 0; np < 4; ++np) {          // n-pairs (2n, 2n+1)
                uint32_t p[4];
                #pragma unroll
                for (int j = 0; j < 2; ++j) {
                    int n = 2 * np + j;
                    float c0 = 0.f, c1 = 0.f, c2 = 0.f, c3 = 0.f;
                    asm volatile(
                        "mma.sync.aligned.m16n8k8.row.col.f32.tf32.tf32.f32 "
                        "{%0,%1,%2,%3}, {%4,%5,%6,%7}, {%8,%9}, {%0,%1,%2,%3};"
                        : "+f"(c0), "+f"(c1), "+f"(c2), "+f"(c3)
                        : "r"(a0), "r"(a1), "r"(a1pad), "r"(a1pad),
                          "r"(w1x[n]), "r"(w1y[n]));
                    p[2 * j]     = pack_f16(fmaxf(c0, 0.f), fmaxf(c1, 0.f)); // rows g
                    p[2 * j + 1] = pack_f16(fmaxf(c2, 0.f), fmaxf(c3, 0.f)); // rows g+8
                }
                // tiles: (rows w*16, cols 2np*8), (+8 rows), (cols (2np+1)*8), (+8)
                asm volatile(
                    "stmatrix.sync.aligned.m8n8.x4.shared.b16 [%0], {%1,%2,%3,%4};"
                    :: "r"(st_base + (uint32_t)(2 * np * 16)),
                       "r"(p[0]), "r"(p[1]), "r"(p[2]), "r"(p[3])
                    : "memory");
            }
        }
        __syncthreads();

        // ---- layer 2: warp covers rows mg*64..+63 (4 m-tiles), 2 n-tiles ----
        float s0[2] = {0.f, 0.f}, s1[2] = {0.f, 0.f};
        #pragma unroll
        for (int mt = 0; mt < 4; ++mt) {
            const uint32_t ld_base = h2base + (uint32_t)((mg * 64 + mt * 16) * HW * 4) + lmoff;
            float c[2][4];
            #pragma unroll
            for (int n2 = 0; n2 < 2; ++n2) {
                c[n2][0] = 0.f; c[n2][1] = 0.f; c[n2][2] = 0.f; c[n2][3] = 0.f;
            }
            #pragma unroll
            for (int kt = 0; kt < 4; ++kt) {
                uint32_t a0, a1, a2, a3;
                asm volatile(
                    "ldmatrix.sync.aligned.m8n8.x4.shared.b16 {%0,%1,%2,%3}, [%4];"
                    : "=r"(a0), "=r"(a1), "=r"(a2), "=r"(a3)
                    : "r"(ld_base + (uint32_t)(kt * 32)));
                #pragma unroll
                for (int n2 = 0; n2 < 2; ++n2) {
                    asm volatile(
                        "mma.sync.aligned.m16n8k16.row.col.f32.f16.f16.f32 "
                        "{%0,%1,%2,%3}, {%4,%5,%6,%7}, {%8,%9}, {%0,%1,%2,%3};"
                        : "+f"(c[n2][0]), "+f"(c[n2][1]), "+f"(c[n2][2]), "+f"(c[n2][3])
                        : "r"(a0), "r"(a1), "r"(a2), "r"(a3),
                          "r"(b2f0[n2][kt]), "r"(b2f1[n2][kt]));
                }
            }
            // bias k-group + relu + fold rows into per-batch partials
            #pragma unroll
            for (int n2 = 0; n2 < 2; ++n2) {
                asm volatile(
                    "mma.sync.aligned.m16n8k16.row.col.f32.f16.f16.f32 "
                    "{%0,%1,%2,%3}, {%4,%5,%6,%7}, {%8,%9}, {%0,%1,%2,%3};"
                    : "+f"(c[n2][0]), "+f"(c[n2][1]), "+f"(c[n2][2]), "+f"(c[n2][3])
                    : "r"(abias), "r"(abias), "r"(0u), "r"(0u),
                      "r"(bbias[n2]), "r"(0u));
                s0[n2] += fmaxf(c[n2][0], 0.f) + fmaxf(c[n2][2], 0.f);
                s1[n2] += fmaxf(c[n2][1], 0.f) + fmaxf(c[n2][3], 0.f);
            }
        }

        // ---- reduce: over g via shuffles, across warps via smem atomics ----
        #pragma unroll
        for (int n2 = 0; n2 < 2; ++n2) {
            float v0 = s0[n2], v1 = s1[n2];
            v0 += __shfl_xor_sync(0xffffffffu, v0, 4);
            v1 += __shfl_xor_sync(0xffffffffu, v1, 4);
            v0 += __shfl_xor_sync(0xffffffffu, v0, 8);
            v1 += __shfl_xor_sync(0xffffffffu, v1, 8);
            v0 += __shfl_xor_sync(0xffffffffu, v0, 16);
            v1 += __shfl_xor_sync(0xffffffffu, v1, 16);
            if (g == 0) {
                int col0 = (ng * 2 + n2) * 8 + 2 * t;
                atomicAdd(&sacc[col0],     v0);
                atomicAdd(&sacc[col0 + 1], v1);
            }
        }

        __syncthreads();
        if (tid < HH) {
            out[b * HH + tid] = sacc[tid];
            sacc[tid] = 0.0f;
        }
        // next-iter post-feats sync orders this store before new atomics
    }
}

extern "C" void kernel_launch(void* const* d_in, const int* in_sizes, int n_in,
                              void* d_out, int out_size) {
    (void)in_sizes; (void)n_in; (void)out_size;
    const float* planet_xy = (const float*)d_in[0];
    const float* planet_m  = (const float*)d_in[1];
    const float* ast_xy    = (const float*)d_in[2];
    const float* W1        = (const float*)d_in[3];
    const float* b1        = (const float*)d_in[4];
    const float* W2        = (const float*)d_in[5];
    const float* b2        = (const float*)d_in[6];
    float* out             = (float*)d_out;

    gnn_kernel<<<GRID, 256>>>(planet_xy, planet_m, ast_xy, W1, b1, W2, b2, out);
}

// round 13
// speedup vs baseline: 1.1362x; 1.1362x over previous
#include <cuda_runtime.h>
#include <cuda_fp16.h>
#include <cstdint>

// SimpleGNNBlock: out[b,k] = sum_p relu( relu(feats[b,p,:] @ W1 + b1) @ W2 + b2 )
// feats = [dx, dy, 1/sqrt(dx^2+dy^2+1e-6), m_p],  B=32768, P=128, H=64.
//
// R13: champion R5 dataflow (layer1 tf32 MMA w/ folded b1 -> h fp16 smem ->
// layer2 f16 MMA, scalar LDS/STS fragments, 3 CTAs/SM) with TWO batches per
// barrier phase: halves syncthreads per batch, feats uses all 256 threads,
// layer 2 has 8 independent m-tiles per warp. Bias-MMA replaced by scalar
// b2 add in the epilogue (-20% layer-2 tensor work).

#define BATCHES 32768
#define PP 128
#define HH 64
#define GRID 4096
#define BPC (BATCHES / GRID)    // 8 batches per CTA, 4 phases of 2
#define HW 36                   // h row stride in words; 36%32==4 -> conflict-free

__device__ __forceinline__ uint32_t f2tf32(float x) {
    uint32_t u;
    asm("cvt.rna.tf32.f32 %0, %1;" : "=r"(u) : "f"(x));
    return u;
}
// pack two fp32 -> f16x2 {lo, hi}
__device__ __forceinline__ uint32_t pack_f16(float lo, float hi) {
    uint32_t u;
    asm("cvt.rn.f16x2.f32 %0, %1, %2;" : "=r"(u) : "f"(hi), "f"(lo));
    return u;
}

__global__ __launch_bounds__(256, 3)
void gnn_kernel(const float* __restrict__ planet_xy,   // (B,P,2)
                const float* __restrict__ planet_m,    // (P)
                const float* __restrict__ ast_xy,      // (B,2)
                const float* __restrict__ W1,          // (4,H)
                const float* __restrict__ b1,          // (H)
                const float* __restrict__ W2,          // (H,H) [j][k]
                const float* __restrict__ b2,          // (H)
                float* __restrict__ out)               // (B,H)
{
    __shared__ uint32_t h2[256 * HW];   // h (2 batches) as fp16x2, stride HW
    __shared__ uint4    feats_s[256];   // tf32 bits {dx,dy,inv,m}, 2 batches
    __shared__ float    sacc[2 * HH];

    const int tid  = threadIdx.x;
    const int lane = tid & 31;
    const int w    = tid >> 5;     // warp 0..7
    const int g    = lane >> 2;    // group 0..7
    const int t    = lane & 3;     // thread-in-group 0..3
    const int mg   = w >> 2;       // m-group 0..1 (rows mg*64..+63 per batch)
    const int ng   = w & 3;        // n-group 0..3 (cols ng*16..+15)

    // ---- W2 fp16 B-fragments (m16n8k16 row.col), 16 regs ----
    uint32_t b2f0[2][4], b2f1[2][4];
    float2 bb[2];
    #pragma unroll
    for (int n2 = 0; n2 < 2; ++n2) {
        int col = (ng * 2 + n2) * 8 + g;
        #pragma unroll
        for (int kt = 0; kt < 4; ++kt) {
            b2f0[n2][kt] = pack_f16(W2[(kt * 16 + 2 * t)     * HH + col],
                                    W2[(kt * 16 + 2 * t + 1) * HH + col]);
            b2f1[n2][kt] = pack_f16(W2[(kt * 16 + 2 * t + 8) * HH + col],
                                    W2[(kt * 16 + 2 * t + 9) * HH + col]);
        }
        int c0 = (ng * 2 + n2) * 8 + 2 * t;
        bb[n2] = make_float2(b2[c0], b2[c0 + 1]);
    }

    // ---- W1 tf32 B-fragments (m16n8k8), bias b1 folded as row 4+ ----
    uint32_t w1x[8], w1y[8];
    #pragma unroll
    for (int n = 0; n < 8; ++n) {
        int col = n * 8 + g;
        w1x[n] = f2tf32(W1[t * HH + col]);
        w1y[n] = (t == 0) ? f2tf32(b1[col]) : 0u;
    }
    const uint32_t a1pad = (t == 0) ? 0x3f800000u : 0u;   // tf32 1.0 bias col

    const uint32_t m32 = f2tf32(planet_m[tid & 127]);     // p = tid&127
    if (tid < 2 * HH) sacc[tid] = 0.0f;

    for (int ph = 0; ph < BPC / 2; ++ph) {
        const int b0 = blockIdx.x + (2 * ph) * GRID;      // batch for bid=0
        // bid=1 batch is b0 + GRID

        // ---- feats: all 256 threads, one per (bid, p) ----
        {
            int bid = tid >> 7;
            int p   = tid & 127;
            int bb_ = b0 + bid * GRID;
            float2 pxy = reinterpret_cast<const float2*>(planet_xy)[bb_ * PP + p];
            float2 axy = reinterpret_cast<const float2*>(ast_xy)[bb_];
            float dx = pxy.x - axy.x;
            float dy = pxy.y - axy.y;
            float inv = rsqrtf(fmaf(dx, dx, fmaf(dy, dy, 1e-6f)));
            feats_s[tid] = make_uint4(f2tf32(dx), f2tf32(dy), f2tf32(inv), m32);
        }
        __syncthreads();

        // ---- layer 1: warp w owns rows w*16..+15 and 128+w*16..+15 ----
        {
            const uint32_t* fu = reinterpret_cast<const uint32_t*>(feats_s);
            #pragma unroll
            for (int mb = 0; mb < 2; ++mb) {
                const int r0 = mb * 128 + w * 16;
                uint32_t a0 = fu[(r0 + g)     * 4 + t];
                uint32_t a1 = fu[(r0 + g + 8) * 4 + t];
                #pragma unroll
                for (int n = 0; n < 8; ++n) {
                    float c0 = 0.f, c1 = 0.f, c2 = 0.f, c3 = 0.f;
                    asm volatile(
                        "mma.sync.aligned.m16n8k8.row.col.f32.tf32.tf32.f32 "
                        "{%0,%1,%2,%3}, {%4,%5,%6,%7}, {%8,%9}, {%0,%1,%2,%3};"
                        : "+f"(c0), "+f"(c1), "+f"(c2), "+f"(c3)
                        : "r"(a0), "r"(a1), "r"(a1pad), "r"(a1pad),
                          "r"(w1x[n]), "r"(w1y[n]));
                    h2[(r0 + g)     * HW + n * 4 + t] = pack_f16(fmaxf(c0, 0.f), fmaxf(c1, 0.f));
                    h2[(r0 + g + 8) * HW + n * 4 + t] = pack_f16(fmaxf(c2, 0.f), fmaxf(c3, 0.f));
                }
            }
        }
        __syncthreads();

        // ---- layer 2: per batch, rows mg*64..+63 (4 m-tiles), 2 n-tiles ----
        #pragma unroll
        for (int bid = 0; bid < 2; ++bid) {
            float s0[2] = {0.f, 0.f}, s1[2] = {0.f, 0.f};
            #pragma unroll
            for (int mt = 0; mt < 4; ++mt) {
                const int r0 = bid * 128 + mg * 64 + mt * 16 + g;
                float c[2][4];
                #pragma unroll
                for (int n2 = 0; n2 < 2; ++n2) {
                    c[n2][0] = 0.f; c[n2][1] = 0.f; c[n2][2] = 0.f; c[n2][3] = 0.f;
                }
                #pragma unroll
                for (int kt = 0; kt < 4; ++kt) {
                    uint32_t a0 = h2[r0       * HW + kt * 8 + t];
                    uint32_t a1 = h2[(r0 + 8) * HW + kt * 8 + t];
                    uint32_t a2 = h2[r0       * HW + kt * 8 + t + 4];
                    uint32_t a3 = h2[(r0 + 8) * HW + kt * 8 + t + 4];
                    #pragma unroll
                    for (int n2 = 0; n2 < 2; ++n2) {
                        asm volatile(
                            "mma.sync.aligned.m16n8k16.row.col.f32.f16.f16.f32 "
                            "{%0,%1,%2,%3}, {%4,%5,%6,%7}, {%8,%9}, {%0,%1,%2,%3};"
                            : "+f"(c[n2][0]), "+f"(c[n2][1]), "+f"(c[n2][2]), "+f"(c[n2][3])
                            : "r"(a0), "r"(a1), "r"(a2), "r"(a3),
                              "r"(b2f0[n2][kt]), "r"(b2f1[n2][kt]));
                    }
                }
                // scalar bias + relu + fold rows into per-batch partials
                #pragma unroll
                for (int n2 = 0; n2 < 2; ++n2) {
                    s0[n2] += fmaxf(c[n2][0] + bb[n2].x, 0.f) + fmaxf(c[n2][2] + bb[n2].x, 0.f);
                    s1[n2] += fmaxf(c[n2][1] + bb[n2].y, 0.f) + fmaxf(c[n2][3] + bb[n2].y, 0.f);
                }
            }
            // reduce over g (shuffles), cross-warp smem atomics
            #pragma unroll
            for (int n2 = 0; n2 < 2; ++n2) {
                float v0 = s0[n2], v1 = s1[n2];
                v0 += __shfl_xor_sync(0xffffffffu, v0, 4);
                v1 += __shfl_xor_sync(0xffffffffu, v1, 4);
                v0 += __shfl_xor_sync(0xffffffffu, v0, 8);
                v1 += __shfl_xor_sync(0xffffffffu, v1, 8);
                v0 += __shfl_xor_sync(0xffffffffu, v0, 16);
                v1 += __shfl_xor_sync(0xffffffffu, v1, 16);
                if (g == 0) {
                    int col0 = (ng * 2 + n2) * 8 + 2 * t;
                    atomicAdd(&sacc[bid * HH + col0],     v0);
                    atomicAdd(&sacc[bid * HH + col0 + 1], v1);
                }
            }
        }
        __syncthreads();

        // ---- store both batches, re-zero sacc ----
        if (tid < 2 * HH) {
            int bid = tid >> 6;
            int col = tid & 63;
            out[(b0 + bid * GRID) * HH + col] = sacc[tid];
            sacc[tid] = 0.0f;
        }
        // rezero is ordered before next-phase atomics by the next two barriers
    }
}

extern "C" void kernel_launch(void* const* d_in, const int* in_sizes, int n_in,
                              void* d_out, int out_size) {
    (void)in_sizes; (void)n_in; (void)out_size;
    const float* planet_xy = (const float*)d_in[0];
    const float* planet_m  = (const float*)d_in[1];
    const float* ast_xy    = (const float*)d_in[2];
    const float* W1        = (const float*)d_in[3];
    const float* b1        = (const float*)d_in[4];
    const float* W2        = (const float*)d_in[5];
    const float* b2        = (const float*)d_in[6];
    float* out             = (float*)d_out;

    // keep smem from capping occupancy at 3 CTAs x ~41.5 KB
    cudaFuncSetAttribute(gnn_kernel,
                         cudaFuncAttributePreferredSharedMemoryCarveout, 100);

    gnn_kernel<<<GRID, 256>>>(planet_xy, planet_m, ast_xy, W1, b1, W2, b2, out);
}

// round 14
// speedup vs baseline: 1.7799x; 1.5665x over previous
#include <cuda_runtime.h>
#include <cuda_fp16.h>
#include <cstdint>

// SimpleGNNBlock: out[b,k] = sum_p relu( relu(feats[b,p,:] @ W1 + b1) @ W2 + b2 )
// feats = [dx, dy, 1/sqrt(dx^2+dy^2+1e-6), m_p],  B=32768, P=128, H=64.
//
// R14: R5 dataflow with layer 2 computed TRANSPOSED: D^T = W2^T @ h^T.
//  - A-fragments = W2^T : loop-invariant, 16 regs (under the <=16 law).
//  - B-fragments = h^T  : map directly onto the existing h2 fp16x2 layout,
//    2 LDS.32 per MMA k-group (half of R5's A-fragment traffic).
//  - 256 MMAs/CTA-batch (R5: 320 incl. bias MMAs); b2 folds into 2 scalar
//    FADDs per thread per n-tile since output-k rides the g index.
//  - Layer 1 / feats / h2 layout / 3 CTAs/SM unchanged from R5.

#define BATCHES 32768
#define PP 128
#define HH 64
#define GRID 4096
#define BPC (BATCHES / GRID)    // 8
#define HW 36                   // h row stride in words; 36%32==4 -> conflict-free

__device__ __forceinline__ uint32_t f2tf32(float x) {
    uint32_t u;
    asm("cvt.rna.tf32.f32 %0, %1;" : "=r"(u) : "f"(x));
    return u;
}
// pack two fp32 -> f16x2 {lo, hi}
__device__ __forceinline__ uint32_t pack_f16(float lo, float hi) {
    uint32_t u;
    asm("cvt.rn.f16x2.f32 %0, %1, %2;" : "=r"(u) : "f"(hi), "f"(lo));
    return u;
}

__global__ __launch_bounds__(256, 3)
void gnn_kernel(const float* __restrict__ planet_xy,   // (B,P,2)
                const float* __restrict__ planet_m,    // (P)
                const float* __restrict__ ast_xy,      // (B,2)
                const float* __restrict__ W1,          // (4,H)
                const float* __restrict__ b1,          // (H)
                const float* __restrict__ W2,          // (H,H) [j][k]
                const float* __restrict__ b2,          // (H)
                float* __restrict__ out)               // (B,H)
{
    __shared__ uint32_t h2[128 * HW];   // h as fp16x2 pairs, stride HW words
    __shared__ uint4    feats_s[PP];    // tf32 bits {dx,dy,inv,m}
    __shared__ float    sacc[HH];

    const int tid  = threadIdx.x;
    const int lane = tid & 31;
    const int w    = tid >> 5;     // warp 0..7
    const int g    = lane >> 2;    // group 0..7
    const int t    = lane & 3;     // thread-in-group 0..3
    const int wk   = w & 3;        // output-k block: cols wk*16 .. +15
    const int ph   = w >> 2;       // p-half: p = ph*64 .. +63

    // ---- layer-2 A-fragments = W2^T (m16n8k16 row-major A), 16 regs ----
    // A[m][k] with m = output channel (wk*16+..), k = hidden j.
    // thread (g,t): a0=A[g][2t,2t+1] a1=A[g+8][2t,2t+1]
    //               a2=A[g][2t+8,2t+9] a3=A[g+8][2t+8,2t+9]   (j base kt*16)
    uint32_t af[4][4];
    {
        const int m0 = wk * 16;
        #pragma unroll
        for (int kt = 0; kt < 4; ++kt) {
            const int j0 = kt * 16;
            af[kt][0] = pack_f16(W2[(j0 + 2 * t)     * HH + m0 + g],
                                 W2[(j0 + 2 * t + 1) * HH + m0 + g]);
            af[kt][1] = pack_f16(W2[(j0 + 2 * t)     * HH + m0 + g + 8],
                                 W2[(j0 + 2 * t + 1) * HH + m0 + g + 8]);
            af[kt][2] = pack_f16(W2[(j0 + 2 * t + 8) * HH + m0 + g],
                                 W2[(j0 + 2 * t + 9) * HH + m0 + g]);
            af[kt][3] = pack_f16(W2[(j0 + 2 * t + 8) * HH + m0 + g + 8],
                                 W2[(j0 + 2 * t + 9) * HH + m0 + g + 8]);
        }
    }
    const float bk0 = b2[wk * 16 + g];       // bias for k = wk*16+g
    const float bk1 = b2[wk * 16 + g + 8];   // bias for k = wk*16+g+8

    // ---- W1 tf32 B-fragments (m16n8k8), b1 folded as bias row ----
    uint32_t w1x[8], w1y[8];
    #pragma unroll
    for (int n = 0; n < 8; ++n) {
        int col = n * 8 + g;
        w1x[n] = f2tf32(W1[t * HH + col]);
        w1y[n] = (t == 0) ? f2tf32(b1[col]) : 0u;
    }
    const uint32_t a1pad = (t == 0) ? 0x3f800000u : 0u;   // tf32 1.0 bias col

    uint32_t m32 = 0;
    if (tid < PP) m32 = f2tf32(planet_m[tid]);
    if (tid < HH) sacc[tid] = 0.0f;

    for (int it = 0; it < BPC; ++it) {
        const int b = blockIdx.x + it * GRID;

        // ---- feats (tf32 bits), one thread per p ----
        if (tid < PP) {
            float2 pxy = reinterpret_cast<const float2*>(planet_xy)[b * PP + tid];
            float ax = ast_xy[2 * b], ay = ast_xy[2 * b + 1];
            float dx = pxy.x - ax;
            float dy = pxy.y - ay;
            float inv = rsqrtf(fmaf(dx, dx, fmaf(dy, dy, 1e-6f)));
            feats_s[tid] = make_uint4(f2tf32(dx), f2tf32(dy), f2tf32(inv), m32);
        }
        __syncthreads();

        // ---- layer 1: warp w owns p-rows w*16..+15, all 8 col-tiles ----
        {
            const uint32_t* fu = reinterpret_cast<const uint32_t*>(feats_s);
            uint32_t a0 = fu[(w * 16 + g)     * 4 + t];
            uint32_t a1 = fu[(w * 16 + g + 8) * 4 + t];
            #pragma unroll
            for (int n = 0; n < 8; ++n) {
                float c0 = 0.f, c1 = 0.f, c2 = 0.f, c3 = 0.f;
                asm volatile(
                    "mma.sync.aligned.m16n8k8.row.col.f32.tf32.tf32.f32 "
                    "{%0,%1,%2,%3}, {%4,%5,%6,%7}, {%8,%9}, {%0,%1,%2,%3};"
                    : "+f"(c0), "+f"(c1), "+f"(c2), "+f"(c3)
                    : "r"(a0), "r"(a1), "r"(a1pad), "r"(a1pad),
                      "r"(w1x[n]), "r"(w1y[n]));
                h2[(w * 16 + g)     * HW + n * 4 + t] = pack_f16(fmaxf(c0, 0.f), fmaxf(c1, 0.f));
                h2[(w * 16 + g + 8) * HW + n * 4 + t] = pack_f16(fmaxf(c2, 0.f), fmaxf(c3, 0.f));
            }
        }
        __syncthreads();

        // ---- layer 2 transposed: D^T[k][p] = sum_j W2[j][k] h[p][j] ----
        // warp (wk, ph): m = k in wk*16..+15, n = p in ph*64..+63 (8 n-tiles)
        float s0 = 0.f, s1 = 0.f;
        #pragma unroll
        for (int nt = 0; nt < 8; ++nt) {
            const int p0 = ph * 64 + nt * 8;
            float c0 = 0.f, c1 = 0.f, c2 = 0.f, c3 = 0.f;
            #pragma unroll
            for (int kt = 0; kt < 4; ++kt) {
                // B-frag = h^T: b0 = h[p0+g][j=kt*16+2t,2t+1]  (word kt*8+t)
                //               b1 = h[p0+g][j=kt*16+2t+8,+9]  (word kt*8+t+4)
                uint32_t bb0 = h2[(p0 + g) * HW + kt * 8 + t];
                uint32_t bb1 = h2[(p0 + g) * HW + kt * 8 + t + 4];
                asm volatile(
                    "mma.sync.aligned.m16n8k16.row.col.f32.f16.f16.f32 "
                    "{%0,%1,%2,%3}, {%4,%5,%6,%7}, {%8,%9}, {%0,%1,%2,%3};"
                    : "+f"(c0), "+f"(c1), "+f"(c2), "+f"(c3)
                    : "r"(af[kt][0]), "r"(af[kt][1]), "r"(af[kt][2]), "r"(af[kt][3]),
                      "r"(bb0), "r"(bb1));
            }
            // c0=D^T[k0+g][p0+2t] c1=[p0+2t+1] (k=wk*16+g);  c2,c3 k=+8
            s0 += fmaxf(c0 + bk0, 0.f) + fmaxf(c1 + bk0, 0.f);
            s1 += fmaxf(c2 + bk1, 0.f) + fmaxf(c3 + bk1, 0.f);
        }

        // ---- reduce over p: shuffle over t (xor 1,2), atomics over ph ----
        s0 += __shfl_xor_sync(0xffffffffu, s0, 1);
        s1 += __shfl_xor_sync(0xffffffffu, s1, 1);
        s0 += __shfl_xor_sync(0xffffffffu, s0, 2);
        s1 += __shfl_xor_sync(0xffffffffu, s1, 2);
        if (t == 0) {
            atomicAdd(&sacc[wk * 16 + g],     s0);
            atomicAdd(&sacc[wk * 16 + g + 8], s1);
        }

        __syncthreads();
        if (tid < HH) {
            out[b * HH + tid] = sacc[tid];
            sacc[tid] = 0.0f;
        }
        // re-zero ordered before next-batch atomics by the next two barriers
    }
}

extern "C" void kernel_launch(void* const* d_in, const int* in_sizes, int n_in,
                              void* d_out, int out_size) {
    (void)in_sizes; (void)n_in; (void)out_size;
    const float* planet_xy = (const float*)d_in[0];
    const float* planet_m  = (const float*)d_in[1];
    const float* ast_xy    = (const float*)d_in[2];
    const float* W1        = (const float*)d_in[3];
    const float* b1        = (const float*)d_in[4];
    const float* W2        = (const float*)d_in[5];
    const float* b2        = (const float*)d_in[6];
    float* out             = (float*)d_out;

    gnn_kernel<<<GRID, 256>>>(planet_xy, planet_m, ast_xy, W1, b1, W2, b2, out);
}

// round 16
// speedup vs baseline: 1.8956x; 1.0650x over previous
#include <cuda_runtime.h>
#include <cuda_fp16.h>
#include <cstdint>

// SimpleGNNBlock: out[b,k] = sum_p relu( relu(feats[b,p,:] @ W1 + b1) @ W2 + b2 )
// feats = [dx, dy, 1/sqrt(dx^2+dy^2+1e-6), m_p],  B=32768, P=128, H=64.
//
// R15: R14 (transposed layer 2, W2^T A-frags register-resident) with the h2
// word layout permuted n*4+t -> t*8+n so each lane's fragment words are
// contiguous: layer-1 h stores become 2x STS.128 per row (was 8x STS.32),
// layer-2 B-frag loads become 2x LDS.128 per n-tile (was 8x LDS.32).
// Same bytes/wavefronts, ~60 fewer issue slots per warp per batch.
// Epilogue smem atomics replaced by per-ph sacc banks (plain STS).

#define BATCHES 32768
#define PP 128
#define HH 64
#define GRID 4096
#define BPC (BATCHES / GRID)    // 8
#define HW 36                   // h row stride in words (= 9 uint4)

__device__ __forceinline__ uint32_t f2tf32(float x) {
    uint32_t u;
    asm("cvt.rna.tf32.f32 %0, %1;" : "=r"(u) : "f"(x));
    return u;
}
// pack two fp32 -> f16x2 {lo, hi}
__device__ __forceinline__ uint32_t pack_f16(float lo, float hi) {
    uint32_t u;
    asm("cvt.rn.f16x2.f32 %0, %1, %2;" : "=r"(u) : "f"(hi), "f"(lo));
    return u;
}

__global__ __launch_bounds__(256, 3)
void gnn_kernel(const float* __restrict__ planet_xy,   // (B,P,2)
                const float* __restrict__ planet_m,    // (P)
                const float* __restrict__ ast_xy,      // (B,2)
                const float* __restrict__ W1,          // (4,H)
                const float* __restrict__ b1,          // (H)
                const float* __restrict__ W2,          // (H,H) [j][k]
                const float* __restrict__ b2,          // (H)
                float* __restrict__ out)               // (B,H)
{
    __shared__ __align__(16) uint32_t h2[128 * HW];  // h fp16x2, permuted words
    __shared__ uint4 feats_s[PP];                    // tf32 bits {dx,dy,inv,m}
    __shared__ float sacc[2][HH];                    // per-ph partial banks

    const int tid  = threadIdx.x;
    const int lane = tid & 31;
    const int w    = tid >> 5;     // warp 0..7
    const int g    = lane >> 2;    // group 0..7
    const int t    = lane & 3;     // thread-in-group 0..3
    const int wk   = w & 3;        // output-k block: k = wk*16 .. +15
    const int ph   = w >> 2;       // p-half: p = ph*64 .. +63

    uint4* h4 = reinterpret_cast<uint4*>(h2);        // row stride 9 uint4

    // ---- layer-2 A-fragments = W2^T (m16n8k16 row A), 16 regs ----
    // A[m][j], m = output k (wk*16+..), j = hidden. thread (g,t):
    // af[kt] = {A[g][2t,2t+1], A[g+8][2t,2t+1], A[g][2t+8,+9], A[g+8][2t+8,+9]}
    uint32_t af[4][4];
    {
        const int m0 = wk * 16;
        #pragma unroll
        for (int kt = 0; kt < 4; ++kt) {
            const int j0 = kt * 16;
            af[kt][0] = pack_f16(W2[(j0 + 2 * t)     * HH + m0 + g],
                                 W2[(j0 + 2 * t + 1) * HH + m0 + g]);
            af[kt][1] = pack_f16(W2[(j0 + 2 * t)     * HH + m0 + g + 8],
                                 W2[(j0 + 2 * t + 1) * HH + m0 + g + 8]);
            af[kt][2] = pack_f16(W2[(j0 + 2 * t + 8) * HH + m0 + g],
                                 W2[(j0 + 2 * t + 9) * HH + m0 + g]);
            af[kt][3] = pack_f16(W2[(j0 + 2 * t + 8) * HH + m0 + g + 8],
                                 W2[(j0 + 2 * t + 9) * HH + m0 + g + 8]);
        }
    }
    const float bk0 = b2[wk * 16 + g];
    const float bk1 = b2[wk * 16 + g + 8];

    // ---- W1 tf32 B-fragments (m16n8k8), b1 folded as bias row ----
    uint32_t w1x[8], w1y[8];
    #pragma unroll
    for (int n = 0; n < 8; ++n) {
        int col = n * 8 + g;
        w1x[n] = f2tf32(W1[t * HH + col]);
        w1y[n] = (t == 0) ? f2tf32(b1[col]) : 0u;
    }
    const uint32_t a1pad = (t == 0) ? 0x3f800000u : 0u;   // tf32 1.0 bias col

    uint32_t m32 = 0;
    if (tid < PP) m32 = f2tf32(planet_m[tid]);

    for (int it = 0; it < BPC; ++it) {
        const int b = blockIdx.x + it * GRID;

        // ---- feats (tf32 bits), one thread per p ----
        if (tid < PP) {
            float2 pxy = reinterpret_cast<const float2*>(planet_xy)[b * PP + tid];
            float ax = ast_xy[2 * b], ay = ast_xy[2 * b + 1];
            float dx = pxy.x - ax;
            float dy = pxy.y - ay;
            float inv = rsqrtf(fmaf(dx, dx, fmaf(dy, dy, 1e-6f)));
            feats_s[tid] = make_uint4(f2tf32(dx), f2tf32(dy), f2tf32(inv), m32);
        }
        __syncthreads();

        // ---- layer 1: warp w owns p-rows w*16..+15, all 8 col-tiles.
        //      pack words buffered, then 2x STS.128 per row. ----
        {
            const uint32_t* fu = reinterpret_cast<const uint32_t*>(feats_s);
            uint32_t a0 = fu[(w * 16 + g)     * 4 + t];
            uint32_t a1 = fu[(w * 16 + g + 8) * 4 + t];
            uint32_t pk[8], qk[8];
            #pragma unroll
            for (int n = 0; n < 8; ++n) {
                float c0 = 0.f, c1 = 0.f, c2 = 0.f, c3 = 0.f;
                asm volatile(
                    "mma.sync.aligned.m16n8k8.row.col.f32.tf32.tf32.f32 "
                    "{%0,%1,%2,%3}, {%4,%5,%6,%7}, {%8,%9}, {%0,%1,%2,%3};"
                    : "+f"(c0), "+f"(c1), "+f"(c2), "+f"(c3)
                    : "r"(a0), "r"(a1), "r"(a1pad), "r"(a1pad),
                      "r"(w1x[n]), "r"(w1y[n]));
                pk[n] = pack_f16(fmaxf(c0, 0.f), fmaxf(c1, 0.f));  // row g,  cols 8n+2t..
                qk[n] = pack_f16(fmaxf(c2, 0.f), fmaxf(c3, 0.f));  // row g+8
            }
            // word pos = t*8+n  ->  uint4 index row*9 + 2t (+1)
            const int r0 = w * 16 + g;
            h4[r0 * 9 + 2 * t]           = make_uint4(pk[0], pk[1], pk[2], pk[3]);
            h4[r0 * 9 + 2 * t + 1]       = make_uint4(pk[4], pk[5], pk[6], pk[7]);
            h4[(r0 + 8) * 9 + 2 * t]     = make_uint4(qk[0], qk[1], qk[2], qk[3]);
            h4[(r0 + 8) * 9 + 2 * t + 1] = make_uint4(qk[4], qk[5], qk[6], qk[7]);
        }
        __syncthreads();

        // ---- layer 2 transposed: D^T[k][p] = sum_j W2[j][k] h[p][j] ----
        // warp (wk, ph): m = k in wk*16..+15, n = p in ph*64..+63 (8 n-tiles)
        float s0 = 0.f, s1 = 0.f;
        #pragma unroll
        for (int nt = 0; nt < 8; ++nt) {
            const int p0 = ph * 64 + nt * 8;
            // lane (g,t): 8 B-frag words of row p0+g are contiguous at t*8
            uint4 B0 = h4[(p0 + g) * 9 + 2 * t];       // kt0: {bb0,bb1}, kt1: {bb0,bb1}
            uint4 B1 = h4[(p0 + g) * 9 + 2 * t + 1];   // kt2, kt3
            float c0 = 0.f, c1 = 0.f, c2 = 0.f, c3 = 0.f;
            #pragma unroll
            for (int kt = 0; kt < 4; ++kt) {
                uint32_t bb0 = (kt == 0) ? B0.x : (kt == 1) ? B0.z : (kt == 2) ? B1.x : B1.z;
                uint32_t bb1 = (kt == 0) ? B0.y : (kt == 1) ? B0.w : (kt == 2) ? B1.y : B1.w;
                asm volatile(
                    "mma.sync.aligned.m16n8k16.row.col.f32.f16.f16.f32 "
                    "{%0,%1,%2,%3}, {%4,%5,%6,%7}, {%8,%9}, {%0,%1,%2,%3};"
                    : "+f"(c0), "+f"(c1), "+f"(c2), "+f"(c3)
                    : "r"(af[kt][0]), "r"(af[kt][1]), "r"(af[kt][2]), "r"(af[kt][3]),
                      "r"(bb0), "r"(bb1));
            }
            // c0 = D^T[wk*16+g][p0+2t], c1 = [p0+2t+1]; c2,c3 for k+8
            s0 += fmaxf(c0 + bk0, 0.f) + fmaxf(c1 + bk0, 0.f);
            s1 += fmaxf(c2 + bk1, 0.f) + fmaxf(c3 + bk1, 0.f);
        }

        // ---- reduce over p: shuffle over t, plain STS into per-ph bank ----
        s0 += __shfl_xor_sync(0xffffffffu, s0, 1);
        s1 += __shfl_xor_sync(0xffffffffu, s1, 1);
        s0 += __shfl_xor_sync(0xffffffffu, s0, 2);
        s1 += __shfl_xor_sync(0xffffffffu, s1, 2);
        if (t == 0) {
            sacc[ph][wk * 16 + g]     = s0;
            sacc[ph][wk * 16 + g + 8] = s1;
        }
        __syncthreads();

        if (tid < HH)
            out[b * HH + tid] = sacc[0][tid] + sacc[1][tid];
        // next-iter post-feats barrier orders this read before new sacc STS
    }
}

extern "C" void kernel_launch(void* const* d_in, const int* in_sizes, int n_in,
                              void* d_out, int out_size) {
    (void)in_sizes; (void)n_in; (void)out_size;
    const float* planet_xy = (const float*)d_in[0];
    const float* planet_m  = (const float*)d_in[1];
    const float* ast_xy    = (const float*)d_in[2];
    const float* W1        = (const float*)d_in[3];
    const float* b1        = (const float*)d_in[4];
    const float* W2        = (const float*)d_in[5];
    const float* b2        = (const float*)d_in[6];
    float* out             = (float*)d_out;

    gnn_kernel<<<GRID, 256>>>(planet_xy, planet_m, ast_xy, W1, b1, W2, b2, out);
}